// round 3
// baseline (speedup 1.0000x reference)
#include <cuda_runtime.h>
#include <cuda_bf16.h>

#define S_LEN 2048
#define B_TOT 64
#define HID   512
#define IN_D  128
#define OUT_D 64
#define NGRP  16     // batch groups of 4 rows
#define NCS   8      // hidden-column splits of 64 cols
#define ALPHA 0.2f

// Scratch (no allocations allowed): double-buffered h state + group counters
__device__ float    g_hbuf[2][B_TOT * HID];
__device__ unsigned g_cnt[NGRP * 32];

// ---------------- packed f32x2 helpers (Blackwell FFMA2) ----------------
__device__ __forceinline__ unsigned long long fma2(unsigned long long a,
                                                   unsigned long long b,
                                                   unsigned long long c) {
    unsigned long long d;
    asm("fma.rn.f32x2 %0, %1, %2, %3;" : "=l"(d) : "l"(a), "l"(b), "l"(c));
    return d;
}
__device__ __forceinline__ unsigned long long pack2(float a, float b) {
    unsigned long long r;
    asm("mov.b64 %0, {%1, %2};" : "=l"(r) : "r"(__float_as_uint(a)), "r"(__float_as_uint(b)));
    return r;
}
__device__ __forceinline__ float lo2(unsigned long long v) {
    return __uint_as_float((unsigned)(v & 0xffffffffull));
}
__device__ __forceinline__ float hi2(unsigned long long v) {
    return __uint_as_float((unsigned)(v >> 32));
}
// accurate-enough tanh independent of fast-math flags (~1e-6 rel err in active range)
__device__ __forceinline__ float my_tanh(float v) {
    float e = __expf(2.0f * v);          // overflow->inf gives exactly +1 branch-free
    return 1.0f - 2.0f / (e + 1.0f);
}

__global__ void rnn_init_kernel() {
    if (threadIdx.x < NGRP) g_cnt[threadIdx.x * 32] = 0u;
}

__global__ void __launch_bounds__(256, 1) rnn_fused_kernel(
    const float* __restrict__ x,     // [64][2048][128]
    const float* __restrict__ Wih,   // [128][512]
    const float* __restrict__ Wrec,  // [512][512]
    const float* __restrict__ Who,   // [512][64]
    float* __restrict__ out)         // [64][2048][64]
{
    __shared__ float h_s[4 * 516];         // h state [4 rows][512+pad]
    __shared__ float x_s[2 * 4 * 128];     // double-buffered x tile
    __shared__ float red[16 * 260];        // k-split reduction (padded)
    __shared__ float red2[8 * 36];         // readout reduction
    __shared__ float who_s[8 * 516];       // Who o-slice, transposed [o][k]

    const int t  = threadIdx.x;
    const int g  = blockIdx.x >> 3;        // batch group 0..15
    const int cs = blockIdx.x & 7;         // column split 0..7

    // ---- compute-thread mapping (recurrent + input GEMM) ----
    const int nj = t & 15;                 // n-group (4 cols each)
    const int ks = t >> 4;                 // k-split 0..15 (32 k each)
    const int n0 = cs * 64 + nj * 4;       // global hidden col base
    const int k0 = ks * 32;
    const int i0 = ks * 8;

    // ---- W_rec slice -> registers, packed over k pairs ----
    unsigned long long wr[64];
#pragma unroll
    for (int kp = 0; kp < 16; kp++) {
        float4 we = *(const float4*)&Wrec[(k0 + 2 * kp)     * HID + n0];
        float4 wo = *(const float4*)&Wrec[(k0 + 2 * kp + 1) * HID + n0];
        wr[kp * 4 + 0] = pack2(we.x, wo.x);
        wr[kp * 4 + 1] = pack2(we.y, wo.y);
        wr[kp * 4 + 2] = pack2(we.z, wo.z);
        wr[kp * 4 + 3] = pack2(we.w, wo.w);
    }
    // ---- Wih slice -> registers ----
    unsigned long long wi[16];
#pragma unroll
    for (int ip = 0; ip < 4; ip++) {
        float4 we = *(const float4*)&Wih[(i0 + 2 * ip)     * HID + n0];
        float4 wo = *(const float4*)&Wih[(i0 + 2 * ip + 1) * HID + n0];
        wi[ip * 4 + 0] = pack2(we.x, wo.x);
        wi[ip * 4 + 1] = pack2(we.y, wo.y);
        wi[ip * 4 + 2] = pack2(we.z, wo.z);
        wi[ip * 4 + 3] = pack2(we.w, wo.w);
    }
    // ---- Who o-slice -> smem transposed ----
    for (int idx = t; idx < 8 * 512; idx += 256) {
        int ol = idx >> 9, k = idx & 511;
        who_s[ol * 516 + k] = Who[k * OUT_D + cs * 8 + ol];
    }
    // ---- h0 = 0, stage x[s=0] ----
    for (int idx = t; idx < 4 * 516; idx += 256) h_s[idx] = 0.0f;
    const int bb = t >> 6;                 // 0..3 (x staging row)
    const int i2 = (t & 63) * 2;
    {
        float2 v = *(const float2*)&x[((size_t)(g * 4 + bb) * S_LEN + 0) * IN_D + i2];
        *(float2*)&x_s[bb * 128 + i2] = v;
    }
    // finalize-thread mapping
    const int b_loc = t >> 6, nl = t & 63;
    // readout-thread mapping
    const int ol2 = t & 7, b3 = (t >> 3) & 3, ks2 = t >> 5;
    volatile unsigned* cnt = &g_cnt[g * 32];

    __syncthreads();

#pragma unroll 1
    for (int s = 0; s < S_LEN; s++) {
        // prefetch next x tile early (independent of h)
        float2 xn = make_float2(0.0f, 0.0f);
        if (s + 1 < S_LEN)
            xn = *(const float2*)&x[((size_t)(g * 4 + bb) * S_LEN + (s + 1)) * IN_D + i2];

        // ---- pre-activation: h@Wrec (reg W, smem h) + x@Wih ----
        unsigned long long acc[16];
#pragma unroll
        for (int q = 0; q < 16; q++) acc[q] = 0ull;

        const float* xb = &x_s[(s & 1) * 512];
#pragma unroll
        for (int c = 0; c < 8; c++) {
            int kk = k0 + c * 4;
#pragma unroll
            for (int b = 0; b < 4; b++) {
                ulonglong2 h2 = *(const ulonglong2*)&h_s[b * 516 + kk];
#pragma unroll
                for (int j = 0; j < 4; j++) {
                    acc[b * 4 + j] = fma2(h2.x, wr[(c * 2) * 4 + j],     acc[b * 4 + j]);
                    acc[b * 4 + j] = fma2(h2.y, wr[(c * 2 + 1) * 4 + j], acc[b * 4 + j]);
                }
            }
        }
#pragma unroll
        for (int c = 0; c < 2; c++) {
            int ii = i0 + c * 4;
#pragma unroll
            for (int b = 0; b < 4; b++) {
                ulonglong2 x2 = *(const ulonglong2*)&xb[b * 128 + ii];
#pragma unroll
                for (int j = 0; j < 4; j++) {
                    acc[b * 4 + j] = fma2(x2.x, wi[(c * 2) * 4 + j],     acc[b * 4 + j]);
                    acc[b * 4 + j] = fma2(x2.y, wi[(c * 2 + 1) * 4 + j], acc[b * 4 + j]);
                }
            }
        }
        // stage prefetched x into the other buffer
        *(float2*)&x_s[((s + 1) & 1) * 512 + bb * 128 + i2] = xn;

        // ---- reduce over 16 k-splits ----
#pragma unroll
        for (int b = 0; b < 4; b++) {
            float4 v;
            v.x = lo2(acc[b * 4 + 0]) + hi2(acc[b * 4 + 0]);
            v.y = lo2(acc[b * 4 + 1]) + hi2(acc[b * 4 + 1]);
            v.z = lo2(acc[b * 4 + 2]) + hi2(acc[b * 4 + 2]);
            v.w = lo2(acc[b * 4 + 3]) + hi2(acc[b * 4 + 3]);
            *(float4*)&red[ks * 260 + b * 64 + nj * 4] = v;
        }
        __syncthreads();                                  // S1
        float pre = 0.0f;
#pragma unroll
        for (int r = 0; r < 16; r++) pre += red[r * 260 + t];

        // ---- activation + leaky update, publish own h slice ----
        float hold = h_s[b_loc * 516 + cs * 64 + nl];
        float hnew = (1.0f - ALPHA) * hold + ALPHA * my_tanh(pre);
        float* g_h = g_hbuf[(s + 1) & 1];                 // double buffer
        g_h[(g * 4 + b_loc) * HID + cs * 64 + nl] = hnew;
        __threadfence();
        __syncthreads();                                  // S2

        // ---- 8-CTA group barrier ----
        if (t == 0) {
            atomicAdd((unsigned*)&g_cnt[g * 32], 1u);
            unsigned target = 8u * (unsigned)(s + 1);
            while (*cnt < target) { }
            __threadfence();
        }
        __syncthreads();                                  // S3

        // ---- reload full h (4x512) from global ----
        {
            int off = t * 8;
            float4 a  = *(const float4*)&g_h[g * 4 * HID + off];
            float4 b4 = *(const float4*)&g_h[g * 4 * HID + off + 4];
            int bb2 = off >> 9, kk2 = off & 511;
            *(float4*)&h_s[bb2 * 516 + kk2]     = a;
            *(float4*)&h_s[bb2 * 516 + kk2 + 4] = b4;
        }
        __syncthreads();                                  // S4

        // ---- fused readout: out[:, s, o-slice] = h_{s+1} @ Who ----
        unsigned long long racc = 0ull;
#pragma unroll
        for (int c = 0; c < 16; c++) {
            int kk = ks2 * 64 + c * 4;
            ulonglong2 h2 = *(const ulonglong2*)&h_s[b3 * 516 + kk];
            ulonglong2 w2 = *(const ulonglong2*)&who_s[ol2 * 516 + kk];
            racc = fma2(h2.x, w2.x, racc);
            racc = fma2(h2.y, w2.y, racc);
        }
        red2[ks2 * 36 + b3 * 8 + ol2] = lo2(racc) + hi2(racc);
        __syncthreads();                                  // S5
        if (t < 32) {
            float o = 0.0f;
#pragma unroll
            for (int r = 0; r < 8; r++) o += red2[r * 36 + t];
            out[((size_t)(g * 4 + (t >> 3)) * S_LEN + s) * OUT_D + cs * 8 + (t & 7)] = o;
        }
    }
}

extern "C" void kernel_launch(void* const* d_in, const int* in_sizes, int n_in,
                              void* d_out, int out_size) {
    const float* x    = (const float*)d_in[0];   // [64][2048][128]
    const float* Wih  = (const float*)d_in[1];   // [128][512]
    const float* Wrec = (const float*)d_in[2];   // [512][512]
    const float* Who  = (const float*)d_in[3];   // [512][64]
    float* out = (float*)d_out;                  // [64][2048][64]

    rnn_init_kernel<<<1, 32>>>();
    rnn_fused_kernel<<<NGRP * NCS, 256>>>(x, Wih, Wrec, Who, out);
}